// round 14
// baseline (speedup 1.0000x reference)
#include <cuda_runtime.h>
#include <cuda_bf16.h>
#include <climits>
#include <math.h>
#include <cstdint>

// ---------------- problem constants ----------------
#define T_    2048
#define D_    512
#define H_    8
#define DH_   64
#define L_    4
#define DFF_  2048
#define D3_   1536
#define NCH   32      // attention chunks
#define CHK   64      // chunk length

// output layout (float32): logits[2048*18], val[2048], time[1], states[4*8*64*64]
#define OUT_LOGITS 0
#define OUT_VAL    36864
#define OUT_TIME   38912
#define OUT_STATES 38913

// ---------------- device scratch (static, no allocs) ----------------
__device__ float g_x   [T_*D_];
__device__ float g_qkv [T_*D3_];
__device__ float g_A   [NCH*H_*DH_*DH_];
__device__ float g_Sst [NCH*H_*DH_*DH_];
__device__ int   g_c   [T_];
__device__ int   g_time[T_];

// bf16 split activations
__device__ __align__(16) __nv_bfloat16 g_hh [T_*D_],  g_hl [T_*D_];
__device__ __align__(16) __nv_bfloat16 g_aoh[T_*D_],  g_aol[T_*D_];
__device__ __align__(16) __nv_bfloat16 g_gh [T_*DFF_],g_gl [T_*DFF_];
// bf16 split transposed weights [N][K] per layer
__device__ __align__(16) __nv_bfloat16 g_wqkvT_h[L_*D3_*D_],  g_wqkvT_l[L_*D3_*D_];
__device__ __align__(16) __nv_bfloat16 g_woutT_h[L_*D_*D_],   g_woutT_l[L_*D_*D_];
__device__ __align__(16) __nv_bfloat16 g_wm1T_h [L_*DFF_*D_], g_wm1T_l [L_*DFF_*D_];
__device__ __align__(16) __nv_bfloat16 g_wm2T_h [L_*D_*DFF_], g_wm2T_l [L_*D_*DFF_];

// ---------------- PTX helpers (generic, sm_80+) ----------------
__device__ __forceinline__ uint32_t smem_to_u32(const void* p) {
    uint32_t a;
    asm("{ .reg .u64 t; cvta.to.shared.u64 t, %1; cvt.u32.u64 %0, t; }" : "=r"(a) : "l"(p));
    return a;
}
__device__ __forceinline__ void ldsm_x4(uint32_t* r, uint32_t a) {
    asm volatile("ldmatrix.sync.aligned.m8n8.x4.shared.b16 {%0,%1,%2,%3}, [%4];"
        : "=r"(r[0]), "=r"(r[1]), "=r"(r[2]), "=r"(r[3]) : "r"(a));
}
__device__ __forceinline__ void mma_bf16(float* c, const uint32_t* a, const uint32_t* b) {
    asm volatile("mma.sync.aligned.m16n8k16.row.col.f32.bf16.bf16.f32 "
        "{%0,%1,%2,%3}, {%4,%5,%6,%7}, {%8,%9}, {%0,%1,%2,%3};"
        : "+f"(c[0]), "+f"(c[1]), "+f"(c[2]), "+f"(c[3])
        : "r"(a[0]), "r"(a[1]), "r"(a[2]), "r"(a[3]), "r"(b[0]), "r"(b[1]));
}
__device__ __forceinline__ void cp_async16(uint32_t dst, const void* src) {
    asm volatile("cp.async.cg.shared.global [%0], [%1], 16;" :: "r"(dst), "l"(src) : "memory");
}
#define CP_COMMIT() asm volatile("cp.async.commit_group;" ::: "memory")

// ---------------- misc helpers ----------------
__device__ __forceinline__ float gelu_tanh(float x) {
    const float k0 = 0.7978845608028654f;
    float x3 = x * x * x;
    return 0.5f * x * (1.0f + tanhf(k0 * (x + 0.044715f * x3)));
}
__device__ __forceinline__ void split_bf16(float v, __nv_bfloat16& hi, __nv_bfloat16& lo) {
    hi = __float2bfloat16(v);
    lo = __float2bfloat16(v - __bfloat162float(hi));
}

// ---------------- prep (device func): done dtype detect + parallel scans --------
__device__ void prep_body(const void* __restrict__ done_raw,
                          const int*  __restrict__ state_obs,
                          float* __restrict__ out_time) {
    __shared__ int fl_float, fl_u8;
    __shared__ int wsums[8], wmaxs[8];
    int tid = threadIdx.x;                   // 256 threads
    int lane = tid & 31, warp = tid >> 5;
    if (tid == 0) { fl_float = 0; fl_u8 = 0; }
    __syncthreads();
    const unsigned char* bp = (const unsigned char*)done_raw;
    int lf = 0, lu = 0;
    for (int i = tid; i < T_; i += 256) {
        unsigned char v = bp[i];
        if (v > 1) lf = 1;
        else if (v == 1 && (i & 3)) lu = 1;
    }
    if (lf) atomicOr(&fl_float, 1);
    if (lu) atomicOr(&fl_u8, 1);
    __syncthreads();
    int mode = fl_float ? 0 : (fl_u8 ? 2 : 1);
    int so = state_obs[0];
    int base = tid * 8;
    int d[8];
    #pragma unroll
    for (int j = 0; j < 8; j++) {
        int i = base + j;
        if (mode == 0)      d[j] = (((const float*)done_raw)[i] != 0.0f);
        else if (mode == 1) d[j] = (((const int*)done_raw)[i]   != 0);
        else                d[j] = (bp[i] != 0);
    }
    int csum[8], cmax[8];
    int s = 0, mx = INT_MIN;
    #pragma unroll
    for (int j = 0; j < 8; j++) {
        s += d[j];
        csum[j] = s;
        int v = (so + base + j) * d[j];
        mx = (v > mx) ? v : mx;
        cmax[j] = mx;
    }
    int ts = s, tm = mx;
    #pragma unroll
    for (int off = 1; off < 32; off <<= 1) {
        int us = __shfl_up_sync(0xffffffffu, ts, off);
        int um = __shfl_up_sync(0xffffffffu, tm, off);
        if (lane >= off) { ts += us; tm = (um > tm) ? um : tm; }
    }
    if (lane == 31) { wsums[warp] = ts; wmaxs[warp] = tm; }
    int ps = __shfl_up_sync(0xffffffffu, ts, 1);
    int pm = __shfl_up_sync(0xffffffffu, tm, 1);
    if (lane == 0) { ps = 0; pm = INT_MIN; }
    __syncthreads();
    int woffs = 0, woffm = INT_MIN;
    for (int w = 0; w < warp; w++) {
        woffs += wsums[w];
        woffm = (wmaxs[w] > woffm) ? wmaxs[w] : woffm;
    }
    int pre_s = woffs + ps;
    int pre_m = (pm > woffm) ? pm : woffm;
    #pragma unroll
    for (int j = 0; j < 8; j++) {
        int i = base + j;
        g_c[i] = pre_s + csum[j];
        int m = (cmax[j] > pre_m) ? cmax[j] : pre_m;
        g_time[i] = (so + i) - m;
    }
    if (tid == 255) {
        int m = (cmax[7] > pre_m) ? cmax[7] : pre_m;
        out_time[0] = (float)((so + 2047) - m + 1);
    }
}

// ---------------- fused: 4-group weight transpose+split AND prep (last block) ---
__global__ void wsplitprep_k(
    const float* __restrict__ W0, __nv_bfloat16* __restrict__ Th0, __nv_bfloat16* __restrict__ Tl0, int K0, int N0, int nt0,
    const float* __restrict__ W1, __nv_bfloat16* __restrict__ Th1, __nv_bfloat16* __restrict__ Tl1, int K1, int N1, int nt1,
    const float* __restrict__ W2, __nv_bfloat16* __restrict__ Th2, __nv_bfloat16* __restrict__ Tl2, int K2, int N2, int nt2,
    const float* __restrict__ W3, __nv_bfloat16* __restrict__ Th3, __nv_bfloat16* __restrict__ Tl3, int K3, int N3,
    const void* __restrict__ done_raw, const int* __restrict__ state_obs,
    float* __restrict__ out_time) {
    int b = blockIdx.x;
    if (b == gridDim.x - 1) { prep_body(done_raw, state_obs, out_time); return; }
    const float* W; __nv_bfloat16 *Th, *Tl; int K, N;
    if (b < nt0)                { W = W0; Th = Th0; Tl = Tl0; K = K0; N = N0; }
    else if ((b -= nt0) < nt1)  { W = W1; Th = Th1; Tl = Tl1; K = K1; N = N1; }
    else if ((b -= nt1) < nt2)  { W = W2; Th = Th2; Tl = Tl2; K = K2; N = N2; }
    else { b -= nt2;              W = W3; Th = Th3; Tl = Tl3; K = K3; N = N3; }
    int ntN = N >> 5, ntK = K >> 5;
    int per_l = ntN * ntK;
    int l = b / per_l, r = b % per_l;
    int k0 = (r / ntN) << 5, n0 = (r % ntN) << 5;
    W  += (size_t)l * K * N;
    Th += (size_t)l * N * K;
    Tl += (size_t)l * N * K;
    __shared__ float tile[32][33];
    int tx = threadIdx.x & 31, ty = threadIdx.x >> 5;   // 256 threads
    for (int yy = ty; yy < 32; yy += 8)
        tile[yy][tx] = W[(size_t)(k0 + yy) * N + n0 + tx];
    __syncthreads();
    for (int yy = ty; yy < 32; yy += 8) {
        float v = tile[tx][yy];
        __nv_bfloat16 hi, lo; split_bf16(v, hi, lo);
        size_t o = (size_t)(n0 + yy) * K + k0 + tx;
        Th[o] = hi; Tl[o] = lo;
    }
}

// ---------------- embedding: 8 tokens/block, w_obs streamed once/block ----------
__global__ void embed_k(const float* __restrict__ obs, const float* __restrict__ rew,
                        const int* __restrict__ act,
                        const float* __restrict__ w_obs, const float* __restrict__ b_obs,
                        const float* __restrict__ emb_act,
                        const float* __restrict__ w_rew, const float* __restrict__ b_rew,
                        const float* __restrict__ emb_time) {
    int t0  = blockIdx.x * 8;
    int tid = threadIdx.x;                   // 256
    __shared__ float so[8][64];
    __shared__ int   sa[8], st[8];
    __shared__ float sr[8];
    so[tid >> 6][tid & 63] = obs[(size_t)t0 * 64 + tid];
    {
        int i2 = tid + 256;
        so[i2 >> 6][i2 & 63] = obs[(size_t)t0 * 64 + i2];
    }
    if (tid < 8) {
        sa[tid] = act[t0 + tid];
        st[tid] = g_time[t0 + tid];
        sr[tid] = rew[t0 + tid];
    }
    __syncthreads();
    float acc0[8], acc1[8];
    #pragma unroll
    for (int t = 0; t < 8; t++) { acc0[t] = 0.f; acc1[t] = 0.f; }
    int d0 = tid, d1 = tid + 256;
    #pragma unroll 4
    for (int k = 0; k < 64; k++) {
        float w0 = w_obs[k * D_ + d0];
        float w1 = w_obs[k * D_ + d1];
        #pragma unroll
        for (int t = 0; t < 8; t++) {
            float sv = so[t][k];
            acc0[t] += sv * w0;
            acc1[t] += sv * w1;
        }
    }
    float bo0 = b_obs[d0] + b_rew[d0], bo1 = b_obs[d1] + b_rew[d1];
    float wr0 = w_rew[d0], wr1 = w_rew[d1];
    #pragma unroll
    for (int t = 0; t < 8; t++) {
        const float* ea = emb_act  + (size_t)sa[t] * D_;
        const float* et = emb_time + (size_t)st[t] * D_;
        g_x[(size_t)(t0 + t) * D_ + d0] = acc0[t] + bo0 + ea[d0] + sr[t] * wr0 + et[d0];
        g_x[(size_t)(t0 + t) * D_ + d1] = acc1[t] + bo1 + ea[d1] + sr[t] * wr1 + et[d1];
    }
}

// ---------------- layernorm: warp per token, single allreduce, bf16 split -------
__global__ void layernorm_k(const float* __restrict__ x,
                            const float* __restrict__ s, const float* __restrict__ b,
                            __nv_bfloat16* __restrict__ oh, __nv_bfloat16* __restrict__ ol) {
    int lane = threadIdx.x & 31, warp = threadIdx.x >> 5;
    int t = blockIdx.x * 8 + warp;
    const float4* xr = (const float4*)(x + (size_t)t * D_);
    float4 v[4];
    float sum = 0.f, sq = 0.f;
    #pragma unroll
    for (int i = 0; i < 4; i++) {
        v[i] = xr[lane + 32 * i];
        sum += v[i].x + v[i].y + v[i].z + v[i].w;
        sq  += v[i].x * v[i].x + v[i].y * v[i].y + v[i].z * v[i].z + v[i].w * v[i].w;
    }
    #pragma unroll
    for (int o = 16; o; o >>= 1) {
        sum += __shfl_xor_sync(0xffffffffu, sum, o);
        sq  += __shfl_xor_sync(0xffffffffu, sq,  o);
    }
    float mu  = sum * (1.0f / D_);
    float var = sq * (1.0f / D_) - mu * mu;
    float inv = rsqrtf(var + 1e-6f);
    const float4* s4 = (const float4*)s;
    const float4* b4 = (const float4*)b;
    #pragma unroll
    for (int i = 0; i < 4; i++) {
        float4 sv = s4[lane + 32 * i];
        float4 bv = b4[lane + 32 * i];
        float y0 = (v[i].x - mu) * inv * sv.x + bv.x;
        float y1 = (v[i].y - mu) * inv * sv.y + bv.y;
        float y2 = (v[i].z - mu) * inv * sv.z + bv.z;
        float y3 = (v[i].w - mu) * inv * sv.w + bv.w;
        __nv_bfloat16 h0, l0, h1, l1, h2, l2, h3, l3;
        split_bf16(y0, h0, l0); split_bf16(y1, h1, l1);
        split_bf16(y2, h2, l2); split_bf16(y3, h3, l3);
        size_t e = (size_t)t * D_ + (lane + 32 * i) * 4;
        __nv_bfloat162 ph01 = {h0, h1}, ph23 = {h2, h3};
        __nv_bfloat162 pl01 = {l0, l1}, pl23 = {l2, l3};
        uint2 uh = {*(uint32_t*)&ph01, *(uint32_t*)&ph23};
        uint2 ul = {*(uint32_t*)&pl01, *(uint32_t*)&pl23};
        *(uint2*)(oh + e) = uh;
        *(uint2*)(ol + e) = ul;
    }
}

// ---------------- mma.sync split-bf16 GEMM, tiled BM x BN, warp grid WWM x WWN --
// C[M,N] = A[M,K] @ B^T (B stored [N][K]). BK=32, 8 warps, warp tile WM x WN.
// Split-K supported via gridDim.z (each z-slice covers K/gridDim.z).
// EPI: 0 = store fp32 (+bias), 1 = accumulate into C (+bias, non-atomic),
//      2 = gelu -> bf16 split, 3 = atomicAdd into C (+bias only on z==0)
template <int BM, int BN, int WWM, int NST, int EPI>
__global__ void __launch_bounds__(256, 2)
mmagemm(const __nv_bfloat16* __restrict__ Ah, const __nv_bfloat16* __restrict__ Al,
        const __nv_bfloat16* __restrict__ Bh, const __nv_bfloat16* __restrict__ Bl,
        const float* __restrict__ bias, float* __restrict__ C,
        __nv_bfloat16* __restrict__ Ch, __nv_bfloat16* __restrict__ Cl,
        int M, int N, int K) {
    constexpr int WWN    = 8 / WWM;
    constexpr int WM     = BM / WWM;
    constexpr int WN     = BN / WWN;
    constexpr int MT     = WM / 16;
    constexpr int NT     = WN / 8;
    constexpr int ATILE  = BM * 64;          // bytes per A split tile (BM x 32 bf16)
    constexpr int BTILE  = BN * 64;
    constexpr int BUFB   = 2 * ATILE + 2 * BTILE;
    constexpr int NLINES = (BM + BN) * 8;    // 16B lines per buffer
    extern __shared__ char sm[];
    uint32_t sb = smem_to_u32(sm);
    int tid  = threadIdx.x;
    int lane = tid & 31, wid = tid >> 5;
    int wm = wid / WWN, wn = wid % WWN;
    int bm = blockIdx.y * BM, bn = blockIdx.x * BN;
    int kper = K / gridDim.z;
    int kbase = blockIdx.z * kper;

    auto load_chunk = [&](int buf, int k0) {
        uint32_t base = sb + buf * BUFB;
        #pragma unroll
        for (int j = 0; j < NLINES / 256; j++) {
            int idx = tid + j * 256;
            const __nv_bfloat16* src;
            uint32_t dst;
            if (idx < BM * 8) {
                int tile = idx / (BM * 4), li = idx % (BM * 4);
                int r = li >> 2, c = li & 3;
                src = (tile ? Al : Ah) + (size_t)(bm + r) * K + kbase + k0 + c * 8;
                uint32_t bo = r * 64 + ((c ^ (r & 3)) << 4);
                dst = base + tile * ATILE + bo;
            } else {
                int j2 = idx - BM * 8;
                int tile = j2 / (BN * 4), li = j2 % (BN * 4);
                int r = li >> 2, c = li & 3;
                src = (tile ? Bl : Bh) + (size_t)(bn + r) * K + kbase + k0 + c * 8;
                uint32_t bo = r * 64 + ((c ^ (r & 3)) << 4);
                dst = base + 2 * ATILE + tile * BTILE + bo;
            }
            cp_async16(dst, src);
        }
        CP_COMMIT();
    };

    float acc[MT][NT][4];
    #pragma unroll
    for (int i = 0; i < MT; i++)
        #pragma unroll
        for (int j = 0; j < NT; j++)
            #pragma unroll
            for (int q = 0; q < 4; q++) acc[i][j][q] = 0.f;

    int lrow = (lane & 7) + ((lane >> 3) & 1) * 8;
    uint32_t baseA_row = (uint32_t)((wm * WM + lrow) * 64);
    int b_hi   = lane >> 4;
    int b_pair = (lane >> 3) & 1;
    int b_rin  = lane & 7;
    uint32_t baseB_row = (uint32_t)((wn * WN + b_hi * 8 + b_rin) * 64);
    uint32_t swA[2], swB[2];
    #pragma unroll
    for (int s = 0; s < 2; s++) {
        swA[s] = (uint32_t)(((2 * s + (lane >> 4)) ^ (lane & 3)) << 4);
        swB[s] = (uint32_t)(((2 * s + b_pair) ^ (b_rin & 3)) << 4);
    }

    auto compute_chunk = [&](int buf) {
        uint32_t bufb = sb + buf * BUFB;
        uint32_t A_h = bufb, A_l = bufb + ATILE;
        uint32_t B_h = bufb + 2 * ATILE, B_l = B_h + BTILE;
        #pragma unroll
        for (int s = 0; s < 2; s++) {
            uint32_t bh[NT][2], bl[NT][2];
            #pragma unroll
            for (int np = 0; np < NT / 2; np++) {
                uint32_t ab = baseB_row + np * 1024 + swB[s];
                uint32_t rh[4], rl[4];
                ldsm_x4(rh, B_h + ab);
                ldsm_x4(rl, B_l + ab);
                bh[2*np][0] = rh[0]; bh[2*np][1] = rh[1];
                bh[2*np+1][0] = rh[2]; bh[2*np+1][1] = rh[3];
                bl[2*np][0] = rl[0]; bl[2*np][1] = rl[1];
                bl[2*np+1][0] = rl[2]; bl[2*np+1][1] = rl[3];
            }
            #pragma unroll
            for (int mt = 0; mt < MT; mt++) {
                uint32_t aa = baseA_row + mt * 1024 + swA[s];
                uint32_t ah[4], al[4];
                ldsm_x4(ah, A_h + aa);
                ldsm_x4(al, A_l + aa);
                #pragma unroll
                for (int nt = 0; nt < NT; nt++) {
                    mma_bf16(acc[mt][nt], ah, bh[nt]);
                    mma_bf16(acc[mt][nt], ah, bl[nt]);
                    mma_bf16(acc[mt][nt], al, bh[nt]);
                }
            }
        }
    };

    int nch = kper >> 5;
    load_chunk(0, 0);
    load_chunk(1, 32);
    if (NST == 3) {
        for (int i = 0; i < nch; i++) {
            if (i + 2 <= nch) { asm volatile("cp.async.wait_group 1;" ::: "memory"); }
            else              { asm volatile("cp.async.wait_group 0;" ::: "memory"); }
            __syncthreads();
            if (i + 2 < nch) load_chunk((i + 2) % 3, (i + 2) << 5);
            compute_chunk(i % 3);
        }
    } else {
        for (int i = 0; i < nch; i++) {
            if (i + 1 < nch) { asm volatile("cp.async.wait_group 1;" ::: "memory"); }
            else             { asm volatile("cp.async.wait_group 0;" ::: "memory"); }
            __syncthreads();
            compute_chunk(i & 1);
            if (i + 2 < nch) {
                __syncthreads();
                load_chunk((i + 2) & 1, (i + 2) << 5);
            }
        }
    }

    float bz = (EPI == 3 && blockIdx.z != 0) ? 0.f : 1.f;
    int r0    = bm + wm * WM + (lane >> 2);
    int cbase = bn + wn * WN + (lane & 3) * 2;
    #pragma unroll
    for (int mt = 0; mt < MT; mt++) {
        #pragma unroll
        for (int hh = 0; hh < 2; hh++) {
            int row = r0 + mt * 16 + hh * 8;
            #pragma unroll
            for (int nt = 0; nt < NT; nt++) {
                int col = cbase + nt * 8;
                float v0 = acc[mt][nt][hh * 2 + 0] + bz * bias[col];
                float v1 = acc[mt][nt][hh * 2 + 1] + bz * bias[col + 1];
                size_t o = (size_t)row * N + col;
                if (EPI == 0) {
                    *(float2*)(C + o) = make_float2(v0, v1);
                } else if (EPI == 1) {
                    float2 old = *(float2*)(C + o);
                    *(float2*)(C + o) = make_float2(old.x + v0, old.y + v1);
                } else if (EPI == 3) {
                    atomicAdd(C + o, v0);
                    atomicAdd(C + o + 1, v1);
                } else {
                    float gg0 = gelu_tanh(v0), gg1 = gelu_tanh(v1);
                    __nv_bfloat16 h0, l0, h1, l1;
                    split_bf16(gg0, h0, l0);
                    split_bf16(gg1, h1, l1);
                    __nv_bfloat162 ph = {h0, h1}, pl = {l0, l1};
                    *(__nv_bfloat162*)(Ch + o) = ph;
                    *(__nv_bfloat162*)(Cl + o) = pl;
                }
            }
        }
    }
}

// ---------------- attention phase 1: per-chunk KV sums (last segment of chunk) ----
__global__ void attn_p1(const float* __restrict__ qkv) {
    int chunk = blockIdx.x, h = blockIdx.y;
    int tid = threadIdx.x;
    int e  = tid & 63;
    int dg = tid >> 6;
    __shared__ float sk[32][64], sv[32][64];
    __shared__ int sflag[CHK];
    float S[16];
    #pragma unroll
    for (int i = 0; i < 16; i++) S[i] = 0.f;
    int c_end = g_c[chunk * CHK + CHK - 1];
    if (tid < CHK) sflag[tid] = (g_c[chunk * CHK + tid] == c_end) ? 1 : 0;
    for (int t0 = 0; t0 < CHK; t0 += 32) {
        __syncthreads();
        for (int l = tid; l < 32 * 64; l += 256) {
            int tt = l >> 6, d = l & 63;
            size_t base = (size_t)(chunk * CHK + t0 + tt) * D3_ + h * DH_ + d;
            sk[tt][d] = qkv[base + 512];
            sv[tt][d] = qkv[base + 1024];
        }
        __syncthreads();
        #pragma unroll
        for (int tt = 0; tt < 32; tt++) {
            if (sflag[t0 + tt]) {
                float ve = sv[tt][e];
                #pragma unroll
                for (int i = 0; i < 16; i++) S[i] += sk[tt][dg * 16 + i] * ve;
            }
        }
    }
    float* out = g_A + (size_t)(chunk * H_ + h) * 4096;
    #pragma unroll
    for (int i = 0; i < 16; i++) out[(dg * 16 + i) * 64 + e] = S[i];
}

// ---------------- attention phase 2: sequential chunk recurrence ----------------
__global__ void attn_p2(const float* __restrict__ state_blocks_l,
                        float* __restrict__ states_out_l) {
    int h = blockIdx.x;
    int tid = threadIdx.x;
    float S[16];
    const float* sb = state_blocks_l + (size_t)h * 4096;
    #pragma unroll
    for (int i = 0; i < 16; i++) S[i] = sb[tid + 256 * i];
    for (int c = 0; c < NCH; c++) {
        float* dst = g_Sst + (size_t)(c * H_ + h) * 4096;
        #pragma unroll
        for (int i = 0; i < 16; i++) dst[tid + 256 * i] = S[i];
        int cprev = (c == 0) ? 0 : g_c[c * CHK - 1];
        int cend  = g_c[c * CHK + CHK - 1];
        float keep = (cend == cprev) ? 1.f : 0.f;
        const float* Ac = g_A + (size_t)(c * H_ + h) * 4096;
        #pragma unroll
        for (int i = 0; i < 16; i++) S[i] = keep * S[i] + Ac[tid + 256 * i];
    }
    #pragma unroll
    for (int i = 0; i < 16; i++) states_out_l[(size_t)h * 4096 + tid + 256 * i] = S[i];
}

// ---------------- attention phase 3: intra-chunk quadratic + q @ S_start ----------
// CHK=64: qT[64][64] kT[64][64] vs[64][64] Ss[64][64] PT[64][68] + sc[64]
#define PTS 68
#define SMEM3 ((4 * 4096 + 64 * PTS) * 4 + 64 * 4 + 16)
__global__ void __launch_bounds__(256, 2) attn_p3(const float* __restrict__ qkv) {
    extern __shared__ float smf[];
    float* qT = smf;                 // [d][t]
    float* kT = qT + 4096;           // [d][t]
    float* vs = kT + 4096;           // [t][e]
    float* Ss = vs + 4096;           // [d][e]
    float* PT = Ss + 4096;           // [s][t], row stride 68 (16B-aligned rows)
    int*   sc = (int*)(PT + 64 * PTS);
    __shared__ int s_cprev;
    int chunk = blockIdx.x, h = blockIdx.y;
    int tid = threadIdx.x;           // 256
    int bt = chunk * CHK;

    for (int l = tid; l < CHK * DH_; l += 256) {
        int t = l >> 6, d = l & 63;
        const float* base = qkv + (size_t)(bt + t) * D3_ + h * DH_ + d;
        qT[d * 64 + t] = base[0];
        kT[d * 64 + t] = base[512];
        vs[t * 64 + d] = base[1024];
    }
    for (int l = tid; l < 4096; l += 256) Ss[l] = g_Sst[(size_t)(chunk * H_ + h) * 4096 + l];
    if (tid < CHK) sc[tid] = g_c[bt + tid];
    if (tid == 0)  s_cprev = (chunk == 0) ? 0 : g_c[bt - 1];
    __syncthreads();

    int tr = tid >> 4, tc = tid & 15;   // rows t=tr*4..+3, cols s/e=tc*4..+3
    // Stage A: P[t][s] = (q_t . k_s) * mask -> PT[s][t]
    {
        float acc[4][4];
        #pragma unroll
        for (int i = 0; i < 4; i++)
            #pragma unroll
            for (int j = 0; j < 4; j++) acc[i][j] = 0.f;
        for (int d = 0; d < 64; d++) {
            float4 q = *(const float4*)&qT[d * 64 + tr * 4];
            float4 k = *(const float4*)&kT[d * 64 + tc * 4];
            float rq[4] = {q.x, q.y, q.z, q.w};
            float rk[4] = {k.x, k.y, k.z, k.w};
            #pragma unroll
            for (int i = 0; i < 4; i++)
                #pragma unroll
                for (int j = 0; j < 4; j++) acc[i][j] += rq[i] * rk[j];
        }
        #pragma unroll
        for (int i = 0; i < 4; i++) {
            int t = tr * 4 + i;
            int ct = sc[t];
            #pragma unroll
            for (int j = 0; j < 4; j++) {
                int s = tc * 4 + j;
                float m = (s <= t && sc[s] == ct) ? 1.f : 0.f;
                PT[s * PTS + t] = acc[i][j] * m;
            }
        }
    }
    __syncthreads();
    // Stage B: out[t][e] = sum_s P[t][s] v[s][e] + [c[t]==c_prev] sum_d q[t][d] Ss[d][e]
    {
        float acc[4][4], acc2[4][4];
        #pragma unroll
        for (int i = 0; i < 4; i++)
            #pragma unroll
            for (int j = 0; j < 4; j++) { acc[i][j] = 0.f; acc2[i][j] = 0.f; }
        for (int s = 0; s < 64; s++) {
            float4 p = *(const float4*)&PT[s * PTS + tr * 4];
            float4 v = *(const float4*)&vs[s * 64 + tc * 4];
            float rp[4] = {p.x, p.y, p.z, p.w};
            float rv[4] = {v.x, v.y, v.z, v.w};
            #pragma unroll
            for (int i = 0; i < 4; i++)
                #pragma unroll
                for (int j = 0; j < 4; j++) acc[i][j] += rp[i] * rv[j];
        }
        for (int d = 0; d < 64; d++) {
            float4 q = *(const float4*)&qT[d * 64 + tr * 4];
            float4 s0 = *(const float4*)&Ss[d * 64 + tc * 4];
            float rq[4] = {q.x, q.y, q.z, q.w};
            float rs[4] = {s0.x, s0.y, s0.z, s0.w};
            #pragma unroll
            for (int i = 0; i < 4; i++)
                #pragma unroll
                for (int j = 0; j < 4; j++) acc2[i][j] += rq[i] * rs[j];
        }
        #pragma unroll
        for (int i = 0; i < 4; i++) {
            int t = tr * 4 + i;
            float am = (sc[t] == s_cprev) ? 1.f : 0.f;
            size_t base = (size_t)(bt + t) * D_ + h * DH_ + tc * 4;
            __nv_bfloat16 h0, l0, h1, l1, h2, l2, h3, l3;
            split_bf16(acc[i][0] + am * acc2[i][0], h0, l0);
            split_bf16(acc[i][1] + am * acc2[i][1], h1, l1);
            split_bf16(acc[i][2] + am * acc2[i][2], h2, l2);
            split_bf16(acc[i][3] + am * acc2[i][3], h3, l3);
            __nv_bfloat162 ph01 = {h0, h1}, ph23 = {h2, h3};
            __nv_bfloat162 pl01 = {l0, l1}, pl23 = {l2, l3};
            uint2 uh = {*(uint32_t*)&ph01, *(uint32_t*)&ph23};
            uint2 ul = {*(uint32_t*)&pl01, *(uint32_t*)&pl23};
            *(uint2*)(g_aoh + base) = uh;
            *(uint2*)(g_aol + base) = ul;
        }
    }
}

// ---------------- head: 16 tokens/block, weights staged in smem, fused LN -------
__global__ void head_k(const float* __restrict__ x,
                       const float* __restrict__ lnf_s, const float* __restrict__ lnf_b,
                       const float* __restrict__ w_actor, const float* __restrict__ b_actor,
                       const float* __restrict__ w_critic, const float* __restrict__ b_critic,
                       float* __restrict__ out) {
    __shared__ float ws[512 * 19];           // [k][o], o<18 actor, o=18 critic
    __shared__ float sb19[19];
    int tid = threadIdx.x;                   // 256
    int lane = tid & 31, warp = tid >> 5;
    for (int i = tid; i < 512 * 18; i += 256) {
        int k = i / 18, o = i % 18;
        ws[k * 19 + o] = w_actor[i];
    }
    for (int k = tid; k < 512; k += 256) ws[k * 19 + 18] = w_critic[k];
    if (tid < 18) sb19[tid] = b_actor[tid];
    if (tid == 18) sb19[18] = b_critic[0];
    __syncthreads();

    int t0 = blockIdx.x * 16;
    #pragma unroll
    for (int tt = 0; tt < 2; tt++) {
        int t = t0 + warp * 2 + tt;
        const float4* xr = (const float4*)(x + (size_t)t * D_);
        float4 v[4];
        float sum = 0.f, sq = 0.f;
        #pragma unroll
        for (int i = 0; i < 4; i++) {
            v[i] = xr[lane + 32 * i];
            sum += v[i].x + v[i].y + v[i].z + v[i].w;
            sq  += v[i].x * v[i].x + v[i].y * v[i].y + v[i].z * v[i].z + v[i].w * v[i].w;
        }
        #pragma unroll
        for (int o = 16; o; o >>= 1) {
            sum += __shfl_xor_sync(0xffffffffu, sum, o);
            sq  += __shfl_xor_sync(0xffffffffu, sq,  o);
        }
        float mu  = sum * (1.0f / D_);
        float inv = rsqrtf(sq * (1.0f / D_) - mu * mu + 1e-6f);
        float y[16];
        const float4* s4 = (const float4*)lnf_s;
        const float4* b4 = (const float4*)lnf_b;
        #pragma unroll
        for (int i = 0; i < 4; i++) {
            float4 sv = s4[lane + 32 * i];
            float4 bv = b4[lane + 32 * i];
            y[i*4+0] = (v[i].x - mu) * inv * sv.x + bv.x;
            y[i*4+1] = (v[i].y - mu) * inv * sv.y + bv.y;
            y[i*4+2] = (v[i].z - mu) * inv * sv.z + bv.z;
            y[i*4+3] = (v[i].w - mu) * inv * sv.w + bv.w;
        }
        #pragma unroll
        for (int o = 0; o < 19; o++) {
            float acc = 0.f;
            #pragma unroll
            for (int i = 0; i < 4; i++) {
                int kb = (lane + 32 * i) * 4;
                acc += y[i*4+0] * ws[(kb + 0) * 19 + o];
                acc += y[i*4+1] * ws[(kb + 1) * 19 + o];
                acc += y[i*4+2] * ws[(kb + 2) * 19 + o];
                acc += y[i*4+3] * ws[(kb + 3) * 19 + o];
            }
            #pragma unroll
            for (int off = 16; off; off >>= 1)
                acc += __shfl_xor_sync(0xffffffffu, acc, off);
            if (lane == 0) {
                float r = acc + sb19[o];
                if (o < 18) out[OUT_LOGITS + t * 18 + o] = r;
                else        out[OUT_VAL + t] = r;
            }
        }
    }
}

// ---------------- launch ----------------
extern "C" void kernel_launch(void* const* d_in, const int* in_sizes, int n_in,
                              void* d_out, int out_size) {
    const float* obs      = (const float*)d_in[0];
    const float* rew_p    = (const float*)d_in[1];
    const int*   act_p    = (const int*)  d_in[2];
    const void*  done     =               d_in[3];
    const int*   stobs    = (const int*)  d_in[4];
    const float* stblocks = (const float*)d_in[5];
    const float* w_obs    = (const float*)d_in[6];
    const float* b_obs    = (const float*)d_in[7];
    const float* emb_act  = (const float*)d_in[8];
    const float* w_rew    = (const float*)d_in[9];
    const float* b_rew    = (const float*)d_in[10];
    const float* emb_time = (const float*)d_in[11];
    const float* ln1_s    = (const float*)d_in[12];
    const float* ln1_b    = (const float*)d_in[13];
    const float* w_qkv    = (const float*)d_in[14];
    const float* b_qkv    = (const float*)d_in[15];
    const float* w_out    = (const float*)d_in[16];
    const float* b_out    = (const float*)d_in[17];
    const float* ln2_s    = (const float*)d_in[18];
    const float* ln2_b    = (const float*)d_in[19];
    const float* w_m1     = (const float*)d_in[20];
    const float* b_m1     = (const float*)d_in[21];
    const float* w_m2     = (const float*)d_in[22];
    const float* b_m2     = (const float*)d_in[23];
    const float* lnf_s    = (const float*)d_in[24];
    const float* lnf_b    = (const float*)d_in[25];
    const float* w_actor  = (const float*)d_in[26];
    const float* b_actor  = (const float*)d_in[27];
    const float* w_critic = (const float*)d_in[28];
    const float* b_critic = (const float*)d_in[29];
    float* out = (float*)d_out;

    float *px, *pqkv;
    cudaGetSymbolAddress((void**)&px,   g_x);
    cudaGetSymbolAddress((void**)&pqkv, g_qkv);
    __nv_bfloat16 *phh, *phl, *paoh, *paol, *pgh, *pgl;
    cudaGetSymbolAddress((void**)&phh,  g_hh);
    cudaGetSymbolAddress((void**)&phl,  g_hl);
    cudaGetSymbolAddress((void**)&paoh, g_aoh);
    cudaGetSymbolAddress((void**)&paol, g_aol);
    cudaGetSymbolAddress((void**)&pgh,  g_gh);
    cudaGetSymbolAddress((void**)&pgl,  g_gl);
    __nv_bfloat16 *wqh, *wql, *woh, *wol, *w1h, *w1l, *w2h, *w2l;
    cudaGetSymbolAddress((void**)&wqh, g_wqkvT_h);
    cudaGetSymbolAddress((void**)&wql, g_wqkvT_l);
    cudaGetSymbolAddress((void**)&woh, g_woutT_h);
    cudaGetSymbolAddress((void**)&wol, g_woutT_l);
    cudaGetSymbolAddress((void**)&w1h, g_wm1T_h);
    cudaGetSymbolAddress((void**)&w1l, g_wm1T_l);
    cudaGetSymbolAddress((void**)&w2h, g_wm2T_h);
    cudaGetSymbolAddress((void**)&w2l, g_wm2T_l);

    // smem: (BM+BN)*128 per stage
    const int SMEM_QKV = 3 * (128 + 64) * 128;   // 73728  (BM=128, BN=64, 3 stages)
    const int SMEM_M1  = 3 * (128 + 128) * 128;  // 98304  (BM=128, BN=128, 3 stages)

    cudaFuncSetAttribute((const void*)attn_p3,
                         cudaFuncAttributeMaxDynamicSharedMemorySize, SMEM3);
    cudaFuncSetAttribute((const void*)mmagemm<128, 64, 4, 3, 0>,
                         cudaFuncAttributeMaxDynamicSharedMemorySize, SMEM_QKV);
    cudaFuncSetAttribute((const void*)mmagemm<128, 128, 2, 3, 2>,
                         cudaFuncAttributeMaxDynamicSharedMemorySize, SMEM_M1);
    cudaFuncSetAttribute((const void*)mmagemm<128, 64, 4, 3, 3>,
                         cudaFuncAttributeMaxDynamicSharedMemorySize, SMEM_QKV);

    const int NT_QKV = L_ * (D_ / 32) * (D3_ / 32);   // 3072
    const int NT_OUT = L_ * (D_ / 32) * (D_ / 32);    // 1024
    const int NT_M1  = L_ * (D_ / 32) * (DFF_ / 32);  // 4096
    const int NT_M2  = L_ * (DFF_ / 32) * (D_ / 32);  // 4096
    const int NT_ALL = NT_QKV + NT_OUT + NT_M1 + NT_M2;

    wsplitprep_k<<<NT_ALL + 1, 256>>>(
        w_qkv, wqh, wql, D_, D3_, NT_QKV,
        w_out, woh, wol, D_, D_,  NT_OUT,
        w_m1,  w1h, w1l, D_, DFF_, NT_M1,
        w_m2,  w2h, w2l, DFF_, D_,
        done, stobs, out + OUT_TIME);
    embed_k<<<T_ / 8, 256>>>(obs, rew_p, act_p, w_obs, b_obs, emb_act, w_rew, b_rew, emb_time);

    for (int l = 0; l < L_; l++) {
        layernorm_k<<<T_ / 8, 256>>>(px, ln1_s + l * D_, ln1_b + l * D_, phh, phl);
        mmagemm<128, 64, 4, 3, 0><<<dim3(D3_/64, T_/128), 256, SMEM_QKV>>>(
            phh, phl, wqh + (size_t)l * D3_ * D_, wql + (size_t)l * D3_ * D_,
            b_qkv + l * D3_, pqkv, nullptr, nullptr, T_, D3_, D_);
        attn_p1<<<dim3(NCH, H_), 256>>>(pqkv);
        attn_p2<<<H_, 256>>>(stblocks + (size_t)l * H_ * 4096,
                             out + OUT_STATES + (size_t)l * H_ * 4096);
        attn_p3<<<dim3(NCH, H_), 256, SMEM3>>>(pqkv);
        mmagemm<128, 64, 4, 3, 3><<<dim3(D_/64, T_/128, 2), 256, SMEM_QKV>>>(
            paoh, paol, woh + (size_t)l * D_ * D_, wol + (size_t)l * D_ * D_,
            b_out + l * D_, px, nullptr, nullptr, T_, D_, D_);
        layernorm_k<<<T_ / 8, 256>>>(px, ln2_s + l * D_, ln2_b + l * D_, phh, phl);
        mmagemm<128, 128, 2, 3, 2><<<dim3(DFF_/128, T_/128), 256, SMEM_M1>>>(
            phh, phl, w1h + (size_t)l * DFF_ * D_, w1l + (size_t)l * DFF_ * D_,
            b_m1 + l * DFF_, nullptr, pgh, pgl, T_, DFF_, D_);
        mmagemm<128, 64, 4, 3, 3><<<dim3(D_/64, T_/128, 2), 256, SMEM_QKV>>>(
            pgh, pgl, w2h + (size_t)l * D_ * DFF_, w2l + (size_t)l * D_ * DFF_,
            b_m2 + l * D_, px, nullptr, nullptr, T_, D_, DFF_);
    }

    head_k<<<T_ / 16, 256>>>(px, lnf_s, lnf_b, w_actor, b_actor, w_critic, b_critic, out);
}

// round 16
// speedup vs baseline: 1.1657x; 1.1657x over previous
#include <cuda_runtime.h>
#include <cuda_bf16.h>
#include <climits>
#include <math.h>
#include <cstdint>

// ---------------- problem constants ----------------
#define T_    2048
#define D_    512
#define H_    8
#define DH_   64
#define L_    4
#define DFF_  2048
#define D3_   1536
#define NCH   16      // attention chunks
#define CHK   128     // chunk length

// output layout (float32): logits[2048*18], val[2048], time[1], states[4*8*64*64]
#define OUT_LOGITS 0
#define OUT_VAL    36864
#define OUT_TIME   38912
#define OUT_STATES 38913

// ---------------- device scratch (static, no allocs) ----------------
__device__ float g_x   [T_*D_];
__device__ float g_qkv [T_*D3_];
__device__ float g_A   [NCH*H_*DH_*DH_];
__device__ float g_Sst [NCH*H_*DH_*DH_];
__device__ int   g_c   [T_];
__device__ int   g_time[T_];

// bf16 split activations
__device__ __align__(16) __nv_bfloat16 g_hh [T_*D_],  g_hl [T_*D_];
__device__ __align__(16) __nv_bfloat16 g_aoh[T_*D_],  g_aol[T_*D_];
__device__ __align__(16) __nv_bfloat16 g_gh [T_*DFF_],g_gl [T_*DFF_];
// bf16 split transposed weights [N][K] per layer
__device__ __align__(16) __nv_bfloat16 g_wqkvT_h[L_*D3_*D_],  g_wqkvT_l[L_*D3_*D_];
__device__ __align__(16) __nv_bfloat16 g_woutT_h[L_*D_*D_],   g_woutT_l[L_*D_*D_];
__device__ __align__(16) __nv_bfloat16 g_wm1T_h [L_*DFF_*D_], g_wm1T_l [L_*DFF_*D_];
__device__ __align__(16) __nv_bfloat16 g_wm2T_h [L_*D_*DFF_], g_wm2T_l [L_*D_*DFF_];

// ---------------- PTX helpers (generic, sm_80+) ----------------
__device__ __forceinline__ uint32_t smem_to_u32(const void* p) {
    uint32_t a;
    asm("{ .reg .u64 t; cvta.to.shared.u64 t, %1; cvt.u32.u64 %0, t; }" : "=r"(a) : "l"(p));
    return a;
}
__device__ __forceinline__ void ldsm_x4(uint32_t* r, uint32_t a) {
    asm volatile("ldmatrix.sync.aligned.m8n8.x4.shared.b16 {%0,%1,%2,%3}, [%4];"
        : "=r"(r[0]), "=r"(r[1]), "=r"(r[2]), "=r"(r[3]) : "r"(a));
}
__device__ __forceinline__ void mma_bf16(float* c, const uint32_t* a, const uint32_t* b) {
    asm volatile("mma.sync.aligned.m16n8k16.row.col.f32.bf16.bf16.f32 "
        "{%0,%1,%2,%3}, {%4,%5,%6,%7}, {%8,%9}, {%0,%1,%2,%3};"
        : "+f"(c[0]), "+f"(c[1]), "+f"(c[2]), "+f"(c[3])
        : "r"(a[0]), "r"(a[1]), "r"(a[2]), "r"(a[3]), "r"(b[0]), "r"(b[1]));
}
__device__ __forceinline__ void cp_async16(uint32_t dst, const void* src) {
    asm volatile("cp.async.cg.shared.global [%0], [%1], 16;" :: "r"(dst), "l"(src) : "memory");
}
#define CP_COMMIT() asm volatile("cp.async.commit_group;" ::: "memory")

// ---------------- misc helpers ----------------
__device__ __forceinline__ float gelu_tanh(float x) {
    const float k0 = 0.7978845608028654f;
    float x3 = x * x * x;
    return 0.5f * x * (1.0f + tanhf(k0 * (x + 0.044715f * x3)));
}
__device__ __forceinline__ void split_bf16(float v, __nv_bfloat16& hi, __nv_bfloat16& lo) {
    hi = __float2bfloat16(v);
    lo = __float2bfloat16(v - __bfloat162float(hi));
}

// ---------------- prep (device func): done dtype detect + parallel scans --------
__device__ void prep_body(const void* __restrict__ done_raw,
                          const int*  __restrict__ state_obs,
                          float* __restrict__ out_time) {
    __shared__ int fl_float, fl_u8;
    __shared__ int wsums[8], wmaxs[8];
    int tid = threadIdx.x;                   // 256 threads
    int lane = tid & 31, warp = tid >> 5;
    if (tid == 0) { fl_float = 0; fl_u8 = 0; }
    __syncthreads();
    const unsigned char* bp = (const unsigned char*)done_raw;
    int lf = 0, lu = 0;
    for (int i = tid; i < T_; i += 256) {
        unsigned char v = bp[i];
        if (v > 1) lf = 1;
        else if (v == 1 && (i & 3)) lu = 1;
    }
    if (lf) atomicOr(&fl_float, 1);
    if (lu) atomicOr(&fl_u8, 1);
    __syncthreads();
    int mode = fl_float ? 0 : (fl_u8 ? 2 : 1);
    int so = state_obs[0];
    int base = tid * 8;
    int d[8];
    #pragma unroll
    for (int j = 0; j < 8; j++) {
        int i = base + j;
        if (mode == 0)      d[j] = (((const float*)done_raw)[i] != 0.0f);
        else if (mode == 1) d[j] = (((const int*)done_raw)[i]   != 0);
        else                d[j] = (bp[i] != 0);
    }
    int csum[8], cmax[8];
    int s = 0, mx = INT_MIN;
    #pragma unroll
    for (int j = 0; j < 8; j++) {
        s += d[j];
        csum[j] = s;
        int v = (so + base + j) * d[j];
        mx = (v > mx) ? v : mx;
        cmax[j] = mx;
    }
    int ts = s, tm = mx;
    #pragma unroll
    for (int off = 1; off < 32; off <<= 1) {
        int us = __shfl_up_sync(0xffffffffu, ts, off);
        int um = __shfl_up_sync(0xffffffffu, tm, off);
        if (lane >= off) { ts += us; tm = (um > tm) ? um : tm; }
    }
    if (lane == 31) { wsums[warp] = ts; wmaxs[warp] = tm; }
    int ps = __shfl_up_sync(0xffffffffu, ts, 1);
    int pm = __shfl_up_sync(0xffffffffu, tm, 1);
    if (lane == 0) { ps = 0; pm = INT_MIN; }
    __syncthreads();
    int woffs = 0, woffm = INT_MIN;
    for (int w = 0; w < warp; w++) {
        woffs += wsums[w];
        woffm = (wmaxs[w] > woffm) ? wmaxs[w] : woffm;
    }
    int pre_s = woffs + ps;
    int pre_m = (pm > woffm) ? pm : woffm;
    #pragma unroll
    for (int j = 0; j < 8; j++) {
        int i = base + j;
        g_c[i] = pre_s + csum[j];
        int m = (cmax[j] > pre_m) ? cmax[j] : pre_m;
        g_time[i] = (so + i) - m;
    }
    if (tid == 255) {
        int m = (cmax[7] > pre_m) ? cmax[7] : pre_m;
        out_time[0] = (float)((so + 2047) - m + 1);
    }
}

// ---------------- fused: 4-group weight transpose+split AND prep (last block) ---
__global__ void wsplitprep_k(
    const float* __restrict__ W0, __nv_bfloat16* __restrict__ Th0, __nv_bfloat16* __restrict__ Tl0, int K0, int N0, int nt0,
    const float* __restrict__ W1, __nv_bfloat16* __restrict__ Th1, __nv_bfloat16* __restrict__ Tl1, int K1, int N1, int nt1,
    const float* __restrict__ W2, __nv_bfloat16* __restrict__ Th2, __nv_bfloat16* __restrict__ Tl2, int K2, int N2, int nt2,
    const float* __restrict__ W3, __nv_bfloat16* __restrict__ Th3, __nv_bfloat16* __restrict__ Tl3, int K3, int N3,
    const void* __restrict__ done_raw, const int* __restrict__ state_obs,
    float* __restrict__ out_time) {
    int b = blockIdx.x;
    if (b == gridDim.x - 1) { prep_body(done_raw, state_obs, out_time); return; }
    const float* W; __nv_bfloat16 *Th, *Tl; int K, N;
    if (b < nt0)                { W = W0; Th = Th0; Tl = Tl0; K = K0; N = N0; }
    else if ((b -= nt0) < nt1)  { W = W1; Th = Th1; Tl = Tl1; K = K1; N = N1; }
    else if ((b -= nt1) < nt2)  { W = W2; Th = Th2; Tl = Tl2; K = K2; N = N2; }
    else { b -= nt2;              W = W3; Th = Th3; Tl = Tl3; K = K3; N = N3; }
    int ntN = N >> 5, ntK = K >> 5;
    int per_l = ntN * ntK;
    int l = b / per_l, r = b % per_l;
    int k0 = (r / ntN) << 5, n0 = (r % ntN) << 5;
    W  += (size_t)l * K * N;
    Th += (size_t)l * N * K;
    Tl += (size_t)l * N * K;
    __shared__ float tile[32][33];
    int tx = threadIdx.x & 31, ty = threadIdx.x >> 5;   // 256 threads
    for (int yy = ty; yy < 32; yy += 8)
        tile[yy][tx] = W[(size_t)(k0 + yy) * N + n0 + tx];
    __syncthreads();
    for (int yy = ty; yy < 32; yy += 8) {
        float v = tile[tx][yy];
        __nv_bfloat16 hi, lo; split_bf16(v, hi, lo);
        size_t o = (size_t)(n0 + yy) * K + k0 + tx;
        Th[o] = hi; Tl[o] = lo;
    }
}

// ---------------- embedding: 8 tokens/block, w_obs streamed once/block ----------
__global__ void embed_k(const float* __restrict__ obs, const float* __restrict__ rew,
                        const int* __restrict__ act,
                        const float* __restrict__ w_obs, const float* __restrict__ b_obs,
                        const float* __restrict__ emb_act,
                        const float* __restrict__ w_rew, const float* __restrict__ b_rew,
                        const float* __restrict__ emb_time) {
    int t0  = blockIdx.x * 8;
    int tid = threadIdx.x;                   // 256
    __shared__ float so[8][64];
    __shared__ int   sa[8], st[8];
    __shared__ float sr[8];
    so[tid >> 6][tid & 63] = obs[(size_t)t0 * 64 + tid];
    {
        int i2 = tid + 256;
        so[i2 >> 6][i2 & 63] = obs[(size_t)t0 * 64 + i2];
    }
    if (tid < 8) {
        sa[tid] = act[t0 + tid];
        st[tid] = g_time[t0 + tid];
        sr[tid] = rew[t0 + tid];
    }
    __syncthreads();
    float acc0[8], acc1[8];
    #pragma unroll
    for (int t = 0; t < 8; t++) { acc0[t] = 0.f; acc1[t] = 0.f; }
    int d0 = tid, d1 = tid + 256;
    #pragma unroll 4
    for (int k = 0; k < 64; k++) {
        float w0 = w_obs[k * D_ + d0];
        float w1 = w_obs[k * D_ + d1];
        #pragma unroll
        for (int t = 0; t < 8; t++) {
            float sv = so[t][k];
            acc0[t] += sv * w0;
            acc1[t] += sv * w1;
        }
    }
    float bo0 = b_obs[d0] + b_rew[d0], bo1 = b_obs[d1] + b_rew[d1];
    float wr0 = w_rew[d0], wr1 = w_rew[d1];
    #pragma unroll
    for (int t = 0; t < 8; t++) {
        const float* ea = emb_act  + (size_t)sa[t] * D_;
        const float* et = emb_time + (size_t)st[t] * D_;
        g_x[(size_t)(t0 + t) * D_ + d0] = acc0[t] + bo0 + ea[d0] + sr[t] * wr0 + et[d0];
        g_x[(size_t)(t0 + t) * D_ + d1] = acc1[t] + bo1 + ea[d1] + sr[t] * wr1 + et[d1];
    }
}

// ---------------- layernorm: warp per token, single allreduce, bf16 split -------
__global__ void layernorm_k(const float* __restrict__ x,
                            const float* __restrict__ s, const float* __restrict__ b,
                            __nv_bfloat16* __restrict__ oh, __nv_bfloat16* __restrict__ ol) {
    int lane = threadIdx.x & 31, warp = threadIdx.x >> 5;
    int t = blockIdx.x * 8 + warp;
    const float4* xr = (const float4*)(x + (size_t)t * D_);
    float4 v[4];
    float sum = 0.f, sq = 0.f;
    #pragma unroll
    for (int i = 0; i < 4; i++) {
        v[i] = xr[lane + 32 * i];
        sum += v[i].x + v[i].y + v[i].z + v[i].w;
        sq  += v[i].x * v[i].x + v[i].y * v[i].y + v[i].z * v[i].z + v[i].w * v[i].w;
    }
    #pragma unroll
    for (int o = 16; o; o >>= 1) {
        sum += __shfl_xor_sync(0xffffffffu, sum, o);
        sq  += __shfl_xor_sync(0xffffffffu, sq,  o);
    }
    float mu  = sum * (1.0f / D_);
    float var = sq * (1.0f / D_) - mu * mu;
    float inv = rsqrtf(var + 1e-6f);
    const float4* s4 = (const float4*)s;
    const float4* b4 = (const float4*)b;
    #pragma unroll
    for (int i = 0; i < 4; i++) {
        float4 sv = s4[lane + 32 * i];
        float4 bv = b4[lane + 32 * i];
        float y0 = (v[i].x - mu) * inv * sv.x + bv.x;
        float y1 = (v[i].y - mu) * inv * sv.y + bv.y;
        float y2 = (v[i].z - mu) * inv * sv.z + bv.z;
        float y3 = (v[i].w - mu) * inv * sv.w + bv.w;
        __nv_bfloat16 h0, l0, h1, l1, h2, l2, h3, l3;
        split_bf16(y0, h0, l0); split_bf16(y1, h1, l1);
        split_bf16(y2, h2, l2); split_bf16(y3, h3, l3);
        size_t e = (size_t)t * D_ + (lane + 32 * i) * 4;
        __nv_bfloat162 ph01 = {h0, h1}, ph23 = {h2, h3};
        __nv_bfloat162 pl01 = {l0, l1}, pl23 = {l2, l3};
        uint2 uh = {*(uint32_t*)&ph01, *(uint32_t*)&ph23};
        uint2 ul = {*(uint32_t*)&pl01, *(uint32_t*)&pl23};
        *(uint2*)(oh + e) = uh;
        *(uint2*)(ol + e) = ul;
    }
}

// ---------------- mma.sync split-bf16 GEMM, tiled BM x BN, warp grid WWM x WWN --
// C[M,N] = A[M,K] @ B^T (B stored [N][K]). BK=32, 8 warps, warp tile WM x WN.
// Split-K supported via gridDim.z (each z-slice covers K/gridDim.z).
// EPI: 0 = store fp32 (+bias), 1 = accumulate into C (+bias, non-atomic),
//      2 = gelu -> bf16 split, 3 = atomicAdd into C (+bias only on z==0)
template <int BM, int BN, int WWM, int NST, int EPI>
__global__ void __launch_bounds__(256, 2)
mmagemm(const __nv_bfloat16* __restrict__ Ah, const __nv_bfloat16* __restrict__ Al,
        const __nv_bfloat16* __restrict__ Bh, const __nv_bfloat16* __restrict__ Bl,
        const float* __restrict__ bias, float* __restrict__ C,
        __nv_bfloat16* __restrict__ Ch, __nv_bfloat16* __restrict__ Cl,
        int M, int N, int K) {
    constexpr int WWN    = 8 / WWM;
    constexpr int WM     = BM / WWM;
    constexpr int WN     = BN / WWN;
    constexpr int MT     = WM / 16;
    constexpr int NT     = WN / 8;
    constexpr int ATILE  = BM * 64;          // bytes per A split tile (BM x 32 bf16)
    constexpr int BTILE  = BN * 64;
    constexpr int BUFB   = 2 * ATILE + 2 * BTILE;
    constexpr int NLINES = (BM + BN) * 8;    // 16B lines per buffer
    extern __shared__ char sm[];
    uint32_t sb = smem_to_u32(sm);
    int tid  = threadIdx.x;
    int lane = tid & 31, wid = tid >> 5;
    int wm = wid / WWN, wn = wid % WWN;
    int bm = blockIdx.y * BM, bn = blockIdx.x * BN;
    int kper = K / gridDim.z;
    int kbase = blockIdx.z * kper;

    auto load_chunk = [&](int buf, int k0) {
        uint32_t base = sb + buf * BUFB;
        #pragma unroll
        for (int j = 0; j < NLINES / 256; j++) {
            int idx = tid + j * 256;
            const __nv_bfloat16* src;
            uint32_t dst;
            if (idx < BM * 8) {
                int tile = idx / (BM * 4), li = idx % (BM * 4);
                int r = li >> 2, c = li & 3;
                src = (tile ? Al : Ah) + (size_t)(bm + r) * K + kbase + k0 + c * 8;
                uint32_t bo = r * 64 + ((c ^ (r & 3)) << 4);
                dst = base + tile * ATILE + bo;
            } else {
                int j2 = idx - BM * 8;
                int tile = j2 / (BN * 4), li = j2 % (BN * 4);
                int r = li >> 2, c = li & 3;
                src = (tile ? Bl : Bh) + (size_t)(bn + r) * K + kbase + k0 + c * 8;
                uint32_t bo = r * 64 + ((c ^ (r & 3)) << 4);
                dst = base + 2 * ATILE + tile * BTILE + bo;
            }
            cp_async16(dst, src);
        }
        CP_COMMIT();
    };

    float acc[MT][NT][4];
    #pragma unroll
    for (int i = 0; i < MT; i++)
        #pragma unroll
        for (int j = 0; j < NT; j++)
            #pragma unroll
            for (int q = 0; q < 4; q++) acc[i][j][q] = 0.f;

    int lrow = (lane & 7) + ((lane >> 3) & 1) * 8;
    uint32_t baseA_row = (uint32_t)((wm * WM + lrow) * 64);
    int b_hi   = lane >> 4;
    int b_pair = (lane >> 3) & 1;
    int b_rin  = lane & 7;
    uint32_t baseB_row = (uint32_t)((wn * WN + b_hi * 8 + b_rin) * 64);
    uint32_t swA[2], swB[2];
    #pragma unroll
    for (int s = 0; s < 2; s++) {
        swA[s] = (uint32_t)(((2 * s + (lane >> 4)) ^ (lane & 3)) << 4);
        swB[s] = (uint32_t)(((2 * s + b_pair) ^ (b_rin & 3)) << 4);
    }

    auto compute_chunk = [&](int buf) {
        uint32_t bufb = sb + buf * BUFB;
        uint32_t A_h = bufb, A_l = bufb + ATILE;
        uint32_t B_h = bufb + 2 * ATILE, B_l = B_h + BTILE;
        #pragma unroll
        for (int s = 0; s < 2; s++) {
            uint32_t bh[NT][2], bl[NT][2];
            #pragma unroll
            for (int np = 0; np < NT / 2; np++) {
                uint32_t ab = baseB_row + np * 1024 + swB[s];
                uint32_t rh[4], rl[4];
                ldsm_x4(rh, B_h + ab);
                ldsm_x4(rl, B_l + ab);
                bh[2*np][0] = rh[0]; bh[2*np][1] = rh[1];
                bh[2*np+1][0] = rh[2]; bh[2*np+1][1] = rh[3];
                bl[2*np][0] = rl[0]; bl[2*np][1] = rl[1];
                bl[2*np+1][0] = rl[2]; bl[2*np+1][1] = rl[3];
            }
            #pragma unroll
            for (int mt = 0; mt < MT; mt++) {
                uint32_t aa = baseA_row + mt * 1024 + swA[s];
                uint32_t ah[4], al[4];
                ldsm_x4(ah, A_h + aa);
                ldsm_x4(al, A_l + aa);
                #pragma unroll
                for (int nt = 0; nt < NT; nt++) {
                    mma_bf16(acc[mt][nt], ah, bh[nt]);
                    mma_bf16(acc[mt][nt], ah, bl[nt]);
                    mma_bf16(acc[mt][nt], al, bh[nt]);
                }
            }
        }
    };

    int nch = kper >> 5;
    load_chunk(0, 0);
    load_chunk(1, 32);
    if (NST == 3) {
        for (int i = 0; i < nch; i++) {
            if (i + 2 <= nch) { asm volatile("cp.async.wait_group 1;" ::: "memory"); }
            else              { asm volatile("cp.async.wait_group 0;" ::: "memory"); }
            __syncthreads();
            if (i + 2 < nch) load_chunk((i + 2) % 3, (i + 2) << 5);
            compute_chunk(i % 3);
        }
    } else {
        for (int i = 0; i < nch; i++) {
            if (i + 1 < nch) { asm volatile("cp.async.wait_group 1;" ::: "memory"); }
            else             { asm volatile("cp.async.wait_group 0;" ::: "memory"); }
            __syncthreads();
            compute_chunk(i & 1);
            if (i + 2 < nch) {
                __syncthreads();
                load_chunk((i + 2) & 1, (i + 2) << 5);
            }
        }
    }

    float bz = (EPI == 3 && blockIdx.z != 0) ? 0.f : 1.f;
    int r0    = bm + wm * WM + (lane >> 2);
    int cbase = bn + wn * WN + (lane & 3) * 2;
    #pragma unroll
    for (int mt = 0; mt < MT; mt++) {
        #pragma unroll
        for (int hh = 0; hh < 2; hh++) {
            int row = r0 + mt * 16 + hh * 8;
            #pragma unroll
            for (int nt = 0; nt < NT; nt++) {
                int col = cbase + nt * 8;
                float v0 = acc[mt][nt][hh * 2 + 0] + bz * bias[col];
                float v1 = acc[mt][nt][hh * 2 + 1] + bz * bias[col + 1];
                size_t o = (size_t)row * N + col;
                if (EPI == 0) {
                    *(float2*)(C + o) = make_float2(v0, v1);
                } else if (EPI == 1) {
                    float2 old = *(float2*)(C + o);
                    *(float2*)(C + o) = make_float2(old.x + v0, old.y + v1);
                } else if (EPI == 3) {
                    atomicAdd(C + o, v0);
                    atomicAdd(C + o + 1, v1);
                } else {
                    float gg0 = gelu_tanh(v0), gg1 = gelu_tanh(v1);
                    __nv_bfloat16 h0, l0, h1, l1;
                    split_bf16(gg0, h0, l0);
                    split_bf16(gg1, h1, l1);
                    __nv_bfloat162 ph = {h0, h1}, pl = {l0, l1};
                    *(__nv_bfloat162*)(Ch + o) = ph;
                    *(__nv_bfloat162*)(Cl + o) = pl;
                }
            }
        }
    }
}

// ---------------- attention phase 1: per-chunk KV sums (float4 loads) -----------
__global__ void attn_p1(const float* __restrict__ qkv) {
    int chunk = blockIdx.x, h = blockIdx.y;
    int tid = threadIdx.x;
    int e  = tid & 63;
    int dg = tid >> 6;
    __shared__ float sk[32][64], sv[32][64];
    __shared__ int sflag[CHK];
    float S[16];
    #pragma unroll
    for (int i = 0; i < 16; i++) S[i] = 0.f;
    int c_end = g_c[chunk * CHK + CHK - 1];
    if (tid < CHK) sflag[tid] = (g_c[chunk * CHK + tid] == c_end) ? 1 : 0;
    for (int t0 = 0; t0 < CHK; t0 += 32) {
        __syncthreads();
        // 32 rows x 16 float4 per tensor = 512 float4 -> 2 per thread
        #pragma unroll
        for (int u = 0; u < 2; u++) {
            int l = tid + u * 256;           // 0..511
            int tt = l >> 4, d4 = l & 15;
            size_t base = (size_t)(chunk * CHK + t0 + tt) * D3_ + h * DH_ + d4 * 4;
            float4 kk = *(const float4*)(qkv + base + 512);
            float4 vv = *(const float4*)(qkv + base + 1024);
            *(float4*)&sk[tt][d4 * 4] = kk;
            *(float4*)&sv[tt][d4 * 4] = vv;
        }
        __syncthreads();
        #pragma unroll
        for (int tt = 0; tt < 32; tt++) {
            if (sflag[t0 + tt]) {
                float ve = sv[tt][e];
                #pragma unroll
                for (int i = 0; i < 16; i++) S[i] += sk[tt][dg * 16 + i] * ve;
            }
        }
    }
    float* out = g_A + (size_t)(chunk * H_ + h) * 4096;
    #pragma unroll
    for (int i = 0; i < 16; i++) out[(dg * 16 + i) * 64 + e] = S[i];
}

// ---------------- attention phase 2: chunk recurrence, 32 blocks ----------------
// NOTE: states_out base (out + OUT_STATES) is NOT 16B-aligned -> scalar final store.
__global__ void attn_p2(const float* __restrict__ state_blocks_l,
                        float* __restrict__ states_out_l) {
    int h = blockIdx.x;                      // 8 heads
    int q = blockIdx.y;                      // 4 quarters of 4096
    int tid = threadIdx.x;                   // 256
    int off = q * 1024 + tid * 4;
    float4 S = *(const float4*)(state_blocks_l + (size_t)h * 4096 + off);
    for (int c = 0; c < NCH; c++) {
        *(float4*)(g_Sst + (size_t)(c * H_ + h) * 4096 + off) = S;
        int cprev = (c == 0) ? 0 : g_c[c * CHK - 1];
        int cend  = g_c[c * CHK + CHK - 1];
        float keep = (cend == cprev) ? 1.f : 0.f;
        float4 A = *(const float4*)(g_A + (size_t)(c * H_ + h) * 4096 + off);
        S.x = keep * S.x + A.x;
        S.y = keep * S.y + A.y;
        S.z = keep * S.z + A.z;
        S.w = keep * S.w + A.w;
    }
    float* dst = states_out_l + (size_t)h * 4096 + off;
    dst[0] = S.x; dst[1] = S.y; dst[2] = S.z; dst[3] = S.w;
}

// ---------------- attention phase 3: intra-chunk quadratic + q @ S_start ----------
#define SMEM3 ((64*128*2 + 128*64 + 64*64 + 128*128) * 4 + 128 * 4)
__global__ void attn_p3(const float* __restrict__ qkv) {
    extern __shared__ float smf[];
    float* qT = smf;
    float* kT = qT + 64 * 128;
    float* vs = kT + 64 * 128;
    float* Ss = vs + 128 * 64;
    float* PT = Ss + 64 * 64;
    int*   sc = (int*)(PT + 128 * 128);
    __shared__ int s_cprev;
    int chunk = blockIdx.x, h = blockIdx.y;
    int tid = threadIdx.x;
    int bt = chunk * CHK;

    for (int l = tid; l < CHK * DH_; l += 256) {
        int t = l >> 6, d = l & 63;
        const float* base = qkv + (size_t)(bt + t) * D3_ + h * DH_ + d;
        qT[d * 128 + t] = base[0];
        kT[d * 128 + t] = base[512];
        vs[t * 64 + d]  = base[1024];
    }
    for (int l = tid; l < 4096; l += 256) Ss[l] = g_Sst[(size_t)(chunk * H_ + h) * 4096 + l];
    if (tid < 128) sc[tid] = g_c[bt + tid];
    if (tid == 0)  s_cprev = (chunk == 0) ? 0 : g_c[bt - 1];
    __syncthreads();

    int tr = tid >> 4, tc = tid & 15;
    {
        float acc[8][8];
        #pragma unroll
        for (int i = 0; i < 8; i++)
            #pragma unroll
            for (int j = 0; j < 8; j++) acc[i][j] = 0.f;
        for (int d = 0; d < 64; d++) {
            float4 q0 = *(const float4*)&qT[d * 128 + tr * 8];
            float4 q1 = *(const float4*)&qT[d * 128 + tr * 8 + 4];
            float4 k0 = *(const float4*)&kT[d * 128 + tc * 8];
            float4 k1 = *(const float4*)&kT[d * 128 + tc * 8 + 4];
            float rq[8] = {q0.x, q0.y, q0.z, q0.w, q1.x, q1.y, q1.z, q1.w};
            float rk[8] = {k0.x, k0.y, k0.z, k0.w, k1.x, k1.y, k1.z, k1.w};
            #pragma unroll
            for (int i = 0; i < 8; i++)
                #pragma unroll
                for (int j = 0; j < 8; j++) acc[i][j] += rq[i] * rk[j];
        }
        #pragma unroll
        for (int i = 0; i < 8; i++) {
            int t = tr * 8 + i;
            int ct = sc[t];
            #pragma unroll
            for (int j = 0; j < 8; j++) {
                int s = tc * 8 + j;
                float m = (s <= t && sc[s] == ct) ? 1.f : 0.f;
                PT[s * 128 + t] = acc[i][j] * m;
            }
        }
    }
    __syncthreads();
    {
        float acc[8][4], acc2[8][4];
        #pragma unroll
        for (int i = 0; i < 8; i++)
            #pragma unroll
            for (int j = 0; j < 4; j++) { acc[i][j] = 0.f; acc2[i][j] = 0.f; }
        for (int s = 0; s < 128; s++) {
            float4 p0 = *(const float4*)&PT[s * 128 + tr * 8];
            float4 p1 = *(const float4*)&PT[s * 128 + tr * 8 + 4];
            float4 v0 = *(const float4*)&vs[s * 64 + tc * 4];
            float rp[8] = {p0.x, p0.y, p0.z, p0.w, p1.x, p1.y, p1.z, p1.w};
            float rv[4] = {v0.x, v0.y, v0.z, v0.w};
            #pragma unroll
            for (int i = 0; i < 8; i++)
                #pragma unroll
                for (int j = 0; j < 4; j++) acc[i][j] += rp[i] * rv[j];
        }
        for (int d = 0; d < 64; d++) {
            float4 q0 = *(const float4*)&qT[d * 128 + tr * 8];
            float4 q1 = *(const float4*)&qT[d * 128 + tr * 8 + 4];
            float4 s0 = *(const float4*)&Ss[d * 64 + tc * 4];
            float rq[8] = {q0.x, q0.y, q0.z, q0.w, q1.x, q1.y, q1.z, q1.w};
            float rs[4] = {s0.x, s0.y, s0.z, s0.w};
            #pragma unroll
            for (int i = 0; i < 8; i++)
                #pragma unroll
                for (int j = 0; j < 4; j++) acc2[i][j] += rq[i] * rs[j];
        }
        #pragma unroll
        for (int i = 0; i < 8; i++) {
            int t = tr * 8 + i;
            float am = (sc[t] == s_cprev) ? 1.f : 0.f;
            size_t base = (size_t)(bt + t) * D_ + h * DH_ + tc * 4;
            #pragma unroll
            for (int j = 0; j < 4; j++) {
                float g = acc[i][j] + am * acc2[i][j];
                __nv_bfloat16 hi, lo; split_bf16(g, hi, lo);
                g_aoh[base + j] = hi; g_aol[base + j] = lo;
            }
        }
    }
}

// ---------------- head: 16 tokens/block, weights staged in smem, fused LN -------
__global__ void head_k(const float* __restrict__ x,
                       const float* __restrict__ lnf_s, const float* __restrict__ lnf_b,
                       const float* __restrict__ w_actor, const float* __restrict__ b_actor,
                       const float* __restrict__ w_critic, const float* __restrict__ b_critic,
                       float* __restrict__ out) {
    __shared__ float ws[512 * 19];           // [k][o], o<18 actor, o=18 critic
    __shared__ float sb19[19];
    int tid = threadIdx.x;                   // 256
    int lane = tid & 31, warp = tid >> 5;
    for (int i = tid; i < 512 * 18; i += 256) {
        int k = i / 18, o = i % 18;
        ws[k * 19 + o] = w_actor[i];
    }
    for (int k = tid; k < 512; k += 256) ws[k * 19 + 18] = w_critic[k];
    if (tid < 18) sb19[tid] = b_actor[tid];
    if (tid == 18) sb19[18] = b_critic[0];
    __syncthreads();

    int t0 = blockIdx.x * 16;
    #pragma unroll
    for (int tt = 0; tt < 2; tt++) {
        int t = t0 + warp * 2 + tt;
        const float4* xr = (const float4*)(x + (size_t)t * D_);
        float4 v[4];
        float sum = 0.f, sq = 0.f;
        #pragma unroll
        for (int i = 0; i < 4; i++) {
            v[i] = xr[lane + 32 * i];
            sum += v[i].x + v[i].y + v[i].z + v[i].w;
            sq  += v[i].x * v[i].x + v[i].y * v[i].y + v[i].z * v[i].z + v[i].w * v[i].w;
        }
        #pragma unroll
        for (int o = 16; o; o >>= 1) {
            sum += __shfl_xor_sync(0xffffffffu, sum, o);
            sq  += __shfl_xor_sync(0xffffffffu, sq,  o);
        }
        float mu  = sum * (1.0f / D_);
        float inv = rsqrtf(sq * (1.0f / D_) - mu * mu + 1e-6f);
        float y[16];
        const float4* s4 = (const float4*)lnf_s;
        const float4* b4 = (const float4*)lnf_b;
        #pragma unroll
        for (int i = 0; i < 4; i++) {
            float4 sv = s4[lane + 32 * i];
            float4 bv = b4[lane + 32 * i];
            y[i*4+0] = (v[i].x - mu) * inv * sv.x + bv.x;
            y[i*4+1] = (v[i].y - mu) * inv * sv.y + bv.y;
            y[i*4+2] = (v[i].z - mu) * inv * sv.z + bv.z;
            y[i*4+3] = (v[i].w - mu) * inv * sv.w + bv.w;
        }
        #pragma unroll
        for (int o = 0; o < 19; o++) {
            float acc = 0.f;
            #pragma unroll
            for (int i = 0; i < 4; i++) {
                int kb = (lane + 32 * i) * 4;
                acc += y[i*4+0] * ws[(kb + 0) * 19 + o];
                acc += y[i*4+1] * ws[(kb + 1) * 19 + o];
                acc += y[i*4+2] * ws[(kb + 2) * 19 + o];
                acc += y[i*4+3] * ws[(kb + 3) * 19 + o];
            }
            #pragma unroll
            for (int off = 16; off; off >>= 1)
                acc += __shfl_xor_sync(0xffffffffu, acc, off);
            if (lane == 0) {
                float r = acc + sb19[o];
                if (o < 18) out[OUT_LOGITS + t * 18 + o] = r;
                else        out[OUT_VAL + t] = r;
            }
        }
    }
}

// ---------------- launch ----------------
extern "C" void kernel_launch(void* const* d_in, const int* in_sizes, int n_in,
                              void* d_out, int out_size) {
    const float* obs      = (const float*)d_in[0];
    const float* rew_p    = (const float*)d_in[1];
    const int*   act_p    = (const int*)  d_in[2];
    const void*  done     =               d_in[3];
    const int*   stobs    = (const int*)  d_in[4];
    const float* stblocks = (const float*)d_in[5];
    const float* w_obs    = (const float*)d_in[6];
    const float* b_obs    = (const float*)d_in[7];
    const float* emb_act  = (const float*)d_in[8];
    const float* w_rew    = (const float*)d_in[9];
    const float* b_rew    = (const float*)d_in[10];
    const float* emb_time = (const float*)d_in[11];
    const float* ln1_s    = (const float*)d_in[12];
    const float* ln1_b    = (const float*)d_in[13];
    const float* w_qkv    = (const float*)d_in[14];
    const float* b_qkv    = (const float*)d_in[15];
    const float* w_out    = (const float*)d_in[16];
    const float* b_out    = (const float*)d_in[17];
    const float* ln2_s    = (const float*)d_in[18];
    const float* ln2_b    = (const float*)d_in[19];
    const float* w_m1     = (const float*)d_in[20];
    const float* b_m1     = (const float*)d_in[21];
    const float* w_m2     = (const float*)d_in[22];
    const float* b_m2     = (const float*)d_in[23];
    const float* lnf_s    = (const float*)d_in[24];
    const float* lnf_b    = (const float*)d_in[25];
    const float* w_actor  = (const float*)d_in[26];
    const float* b_actor  = (const float*)d_in[27];
    const float* w_critic = (const float*)d_in[28];
    const float* b_critic = (const float*)d_in[29];
    float* out = (float*)d_out;

    float *px, *pqkv;
    cudaGetSymbolAddress((void**)&px,   g_x);
    cudaGetSymbolAddress((void**)&pqkv, g_qkv);
    __nv_bfloat16 *phh, *phl, *paoh, *paol, *pgh, *pgl;
    cudaGetSymbolAddress((void**)&phh,  g_hh);
    cudaGetSymbolAddress((void**)&phl,  g_hl);
    cudaGetSymbolAddress((void**)&paoh, g_aoh);
    cudaGetSymbolAddress((void**)&paol, g_aol);
    cudaGetSymbolAddress((void**)&pgh,  g_gh);
    cudaGetSymbolAddress((void**)&pgl,  g_gl);
    __nv_bfloat16 *wqh, *wql, *woh, *wol, *w1h, *w1l, *w2h, *w2l;
    cudaGetSymbolAddress((void**)&wqh, g_wqkvT_h);
    cudaGetSymbolAddress((void**)&wql, g_wqkvT_l);
    cudaGetSymbolAddress((void**)&woh, g_woutT_h);
    cudaGetSymbolAddress((void**)&wol, g_woutT_l);
    cudaGetSymbolAddress((void**)&w1h, g_wm1T_h);
    cudaGetSymbolAddress((void**)&w1l, g_wm1T_l);
    cudaGetSymbolAddress((void**)&w2h, g_wm2T_h);
    cudaGetSymbolAddress((void**)&w2l, g_wm2T_l);

    // smem: (BM+BN)*128 per stage
    const int SMEM_QKV = 3 * (128 + 64) * 128;   // 73728  (BM=128, BN=64, 3 stages)
    const int SMEM_M1  = 3 * (128 + 128) * 128;  // 98304  (BM=128, BN=128, 3 stages)

    cudaFuncSetAttribute((const void*)attn_p3,
                         cudaFuncAttributeMaxDynamicSharedMemorySize, SMEM3);
    cudaFuncSetAttribute((const void*)mmagemm<128, 64, 4, 3, 0>,
                         cudaFuncAttributeMaxDynamicSharedMemorySize, SMEM_QKV);
    cudaFuncSetAttribute((const void*)mmagemm<128, 128, 2, 3, 2>,
                         cudaFuncAttributeMaxDynamicSharedMemorySize, SMEM_M1);
    cudaFuncSetAttribute((const void*)mmagemm<128, 64, 4, 3, 3>,
                         cudaFuncAttributeMaxDynamicSharedMemorySize, SMEM_QKV);

    const int NT_QKV = L_ * (D_ / 32) * (D3_ / 32);   // 3072
    const int NT_OUT = L_ * (D_ / 32) * (D_ / 32);    // 1024
    const int NT_M1  = L_ * (D_ / 32) * (DFF_ / 32);  // 4096
    const int NT_M2  = L_ * (DFF_ / 32) * (D_ / 32);  // 4096
    const int NT_ALL = NT_QKV + NT_OUT + NT_M1 + NT_M2;

    wsplitprep_k<<<NT_ALL + 1, 256>>>(
        w_qkv, wqh, wql, D_, D3_, NT_QKV,
        w_out, woh, wol, D_, D_,  NT_OUT,
        w_m1,  w1h, w1l, D_, DFF_, NT_M1,
        w_m2,  w2h, w2l, DFF_, D_,
        done, stobs, out + OUT_TIME);
    embed_k<<<T_ / 8, 256>>>(obs, rew_p, act_p, w_obs, b_obs, emb_act, w_rew, b_rew, emb_time);

    for (int l = 0; l < L_; l++) {
        layernorm_k<<<T_ / 8, 256>>>(px, ln1_s + l * D_, ln1_b + l * D_, phh, phl);
        mmagemm<128, 64, 4, 3, 0><<<dim3(D3_/64, T_/128), 256, SMEM_QKV>>>(
            phh, phl, wqh + (size_t)l * D3_ * D_, wql + (size_t)l * D3_ * D_,
            b_qkv + l * D3_, pqkv, nullptr, nullptr, T_, D3_, D_);
        attn_p1<<<dim3(NCH, H_), 256>>>(pqkv);
        attn_p2<<<dim3(H_, 4), 256>>>(stblocks + (size_t)l * H_ * 4096,
                                      out + OUT_STATES + (size_t)l * H_ * 4096);
        attn_p3<<<dim3(NCH, H_), 256, SMEM3>>>(pqkv);
        mmagemm<128, 64, 4, 3, 3><<<dim3(D_/64, T_/128, 2), 256, SMEM_QKV>>>(
            paoh, paol, woh + (size_t)l * D_ * D_, wol + (size_t)l * D_ * D_,
            b_out + l * D_, px, nullptr, nullptr, T_, D_, D_);
        layernorm_k<<<T_ / 8, 256>>>(px, ln2_s + l * D_, ln2_b + l * D_, phh, phl);
        mmagemm<128, 128, 2, 3, 2><<<dim3(DFF_/128, T_/128), 256, SMEM_M1>>>(
            phh, phl, w1h + (size_t)l * DFF_ * D_, w1l + (size_t)l * DFF_ * D_,
            b_m1 + l * DFF_, nullptr, pgh, pgl, T_, DFF_, D_);
        mmagemm<128, 64, 4, 3, 3><<<dim3(D_/64, T_/128, 2), 256, SMEM_QKV>>>(
            pgh, pgl, w2h + (size_t)l * D_ * DFF_, w2l + (size_t)l * D_ * DFF_,
            b_m2 + l * D_, px, nullptr, nullptr, T_, D_, DFF_);
    }

    head_k<<<T_ / 16, 256>>>(px, lnf_s, lnf_b, w_actor, b_actor, w_critic, b_critic, out);
}